// round 5
// baseline (speedup 1.0000x reference)
#include <cuda_runtime.h>
#include <cstdint>

// Problem constants (match reference)
#define N_NODES 50000
#define N_EDGES 800000
#define IN_DIM  256
#define HIDDEN  128
#define OUT_DIM 64
#define NEG_SLOPE 0.1f

// ---------------- scratch (no allocations allowed) ----------------
__device__ __align__(16) float g_deg [N_NODES];
__device__ __align__(16) float g_dinv[N_NODES];
__device__ __align__(16) float g_h   [N_NODES * HIDDEN];  // activations
__device__ __align__(16) float g_t   [N_NODES * HIDDEN];  // dense-transform result
__device__ __align__(16) float g_agg [N_NODES * HIDDEN];  // aggregation accumulator
__device__ int g_is32;                                     // 1 if edge_index is int32

// ---------------- edge index access (int32 or int64) ----------------
__device__ __forceinline__ int edge_at(const void* ei, int i, int is32, int half) {
    if (is32) return ((const int*)ei)[half * N_EDGES + i];
    return (int)((const long long*)ei)[half * N_EDGES + i];
}

// Detect dtype of edge_index buffer: interpret as int64; if any of the first 64
// values is outside [0, N_NODES) the buffer must be int32.
__global__ void k_detect(const void* __restrict__ ei, int* __restrict__ flag) {
    if (threadIdx.x == 0 && blockIdx.x == 0) {
        const long long* p = (const long long*)ei;
        int is32 = 0;
        for (int i = 0; i < 64; i++) {
            long long v = p[i];
            if (v < 0 || v >= N_NODES) { is32 = 1; break; }
        }
        *flag = is32;
    }
}

// ---------------- small kernels ----------------
__global__ void k_deg_init(float* __restrict__ deg, int n) {
    int i = blockIdx.x * blockDim.x + threadIdx.x;
    if (i < n) deg[i] = 1.0f;  // self loop contributes 1 to in-degree
}

__global__ void k_deg_accum(const void* __restrict__ ei, float* __restrict__ deg,
                            const int* __restrict__ flag, int e) {
    int i = blockIdx.x * blockDim.x + threadIdx.x;
    if (i >= e) return;
    int d = edge_at(ei, i, *flag, 1);
    if ((unsigned)d < N_NODES) atomicAdd(&deg[d], 1.0f);
}

__global__ void k_dinv(const float* __restrict__ deg, float* __restrict__ dinv, int n) {
    int i = blockIdx.x * blockDim.x + threadIdx.x;
    if (i < n) dinv[i] = rsqrtf(deg[i]);   // deg >= 1 always
}

// agg[i][c] = t[i][c] * dinv[i]^2 + bias[c]   (self-loop message + conv bias)
__global__ void k_selfinit(const float* __restrict__ t, const float* __restrict__ dinv,
                           const float* __restrict__ bias, float* __restrict__ agg) {
    int gid = blockIdx.x * blockDim.x + threadIdx.x;   // over N_NODES*HIDDEN/4
    int total = N_NODES * HIDDEN / 4;
    if (gid >= total) return;
    int node = gid / (HIDDEN / 4);
    int c4   = (gid % (HIDDEN / 4)) * 4;
    float w = dinv[node]; w = w * w;
    float4 v = ((const float4*)t)[gid];
    float4 b = *(const float4*)(bias + c4);
    float4 o;
    o.x = fmaf(v.x, w, b.x); o.y = fmaf(v.y, w, b.y);
    o.z = fmaf(v.z, w, b.z); o.w = fmaf(v.w, w, b.w);
    ((float4*)agg)[gid] = o;
}

// one warp per edge; each lane handles 4 contiguous cols (32*4 = 128)
__global__ void __launch_bounds__(256) k_scatter(
    const void* __restrict__ ei,
    const float* __restrict__ dinv, const float* __restrict__ t,
    float* __restrict__ agg, const int* __restrict__ flag, int E)
{
    int e = blockIdx.x * 8 + (threadIdx.x >> 5);
    if (e >= E) return;
    int is32 = *flag;
    int lane = threadIdx.x & 31;
    int s = edge_at(ei, e, is32, 0);
    int d = edge_at(ei, e, is32, 1);
    if ((unsigned)s >= N_NODES || (unsigned)d >= N_NODES) return;
    float w = dinv[s] * dinv[d];
    float4 v = ((const float4*)(t + (size_t)s * HIDDEN))[lane];
    float* p = agg + (size_t)d * HIDDEN + lane * 4;
    atomicAdd(p + 0, v.x * w);
    atomicAdd(p + 1, v.y * w);
    atomicAdd(p + 2, v.z * w);
    atomicAdd(p + 3, v.w * w);
}

// h = leaky_relu(agg)
__global__ void k_lrelu(const float* __restrict__ in, float* __restrict__ out) {
    int gid = blockIdx.x * blockDim.x + threadIdx.x;
    int total = N_NODES * HIDDEN / 4;
    if (gid >= total) return;
    float4 v = ((const float4*)in)[gid];
    v.x = v.x > 0.f ? v.x : v.x * NEG_SLOPE;
    v.y = v.y > 0.f ? v.y : v.y * NEG_SLOPE;
    v.z = v.z > 0.f ? v.z : v.z * NEG_SLOPE;
    v.w = v.w > 0.f ? v.w : v.w * NEG_SLOPE;
    ((float4*)out)[gid] = v;
}

// ---------------- SGEMM: C[M,N] = A[M,K] @ B[K,N] (+bias, +leaky) ----------------
// BM=64, BN=64, BK=16, 4x4 per thread, 256 threads. N,K multiples of 16/64, M ragged.
__global__ void __launch_bounds__(256) sgemm_kernel(
    const float* __restrict__ A, const float* __restrict__ B,
    const float* __restrict__ bias, float* __restrict__ C,
    int M, int N, int K, int act)
{
    const int BM = 64, BN = 64, BK = 16;
    __shared__ float As[BK][BM];   // transposed: As[k][m]
    __shared__ float Bs[BK][BN];

    int t = threadIdx.x;
    int bm0 = blockIdx.y * BM;
    int bn0 = blockIdx.x * BN;

    int a_row = t >> 2;            // 0..63
    int a_k4  = (t & 3) * 4;       // 0,4,8,12
    int b_row = t >> 4;            // 0..15
    int b_c4  = (t & 15) * 4;      // 0..60

    int trow = t >> 4;             // 0..15 -> rows trow*4..+3
    int tcol = t & 15;             // 0..15 -> cols tcol*4..+3

    float acc[4][4];
#pragma unroll
    for (int i = 0; i < 4; i++)
#pragma unroll
        for (int j = 0; j < 4; j++) acc[i][j] = 0.f;

    for (int k0 = 0; k0 < K; k0 += BK) {
        {
            int gr = bm0 + a_row;
            float4 v = make_float4(0.f, 0.f, 0.f, 0.f);
            if (gr < M) v = *(const float4*)(A + (size_t)gr * K + k0 + a_k4);
            As[a_k4 + 0][a_row] = v.x;
            As[a_k4 + 1][a_row] = v.y;
            As[a_k4 + 2][a_row] = v.z;
            As[a_k4 + 3][a_row] = v.w;
        }
        {
            float4 v = *(const float4*)(B + (size_t)(k0 + b_row) * N + bn0 + b_c4);
            *(float4*)&Bs[b_row][b_c4] = v;
        }
        __syncthreads();

#pragma unroll
        for (int kk = 0; kk < BK; kk++) {
            float4 a = *(const float4*)&As[kk][trow * 4];
            float4 b = *(const float4*)&Bs[kk][tcol * 4];
            float ar[4] = {a.x, a.y, a.z, a.w};
            float br[4] = {b.x, b.y, b.z, b.w};
#pragma unroll
            for (int i = 0; i < 4; i++)
#pragma unroll
                for (int j = 0; j < 4; j++)
                    acc[i][j] = fmaf(ar[i], br[j], acc[i][j]);
        }
        __syncthreads();
    }

    float4 bv = make_float4(0.f, 0.f, 0.f, 0.f);
    if (bias) bv = *(const float4*)(bias + bn0 + tcol * 4);
#pragma unroll
    for (int i = 0; i < 4; i++) {
        int gr = bm0 + trow * 4 + i;
        if (gr >= M) continue;
        float4 o;
        o.x = acc[i][0] + bv.x;
        o.y = acc[i][1] + bv.y;
        o.z = acc[i][2] + bv.z;
        o.w = acc[i][3] + bv.w;
        if (act) {
            o.x = o.x > 0.f ? o.x : o.x * NEG_SLOPE;
            o.y = o.y > 0.f ? o.y : o.y * NEG_SLOPE;
            o.z = o.z > 0.f ? o.z : o.z * NEG_SLOPE;
            o.w = o.w > 0.f ? o.w : o.w * NEG_SLOPE;
        }
        *(float4*)(C + (size_t)gr * N + bn0 + tcol * 4) = o;
    }
}

// ---------------- launch ----------------
extern "C" void kernel_launch(void* const* d_in, const int* in_sizes, int n_in,
                              void* d_out, int out_size)
{
    // Identify inputs by element count (robust to metadata ordering).
    // x: 12,800,000   edge_index: 1,600,000   enc_b: 128   conv_b: 256
    // dec_W: 8,192    dec_b: 64
    // enc_W / conv_W both 32,768: disambiguate by the size of the NEXT entry
    // (a weight is adjacent to its own bias: next==128 -> enc_W, next==256 -> conv_W).
    const float *x = 0, *enc_W = 0, *enc_b = 0, *conv_W = 0, *conv_b = 0, *dec_W = 0, *dec_b = 0;
    const void  *ei = 0;
    for (int i = 0; i < n_in; i++) {
        int sz = in_sizes[i];
        const void* p = d_in[i];
        switch (sz) {
            case 12800000: x      = (const float*)p; break;
            case 1600000:  ei     = p;               break;
            case 128:      enc_b  = (const float*)p; break;
            case 256:      conv_b = (const float*)p; break;
            case 8192:     dec_W  = (const float*)p; break;
            case 64:       dec_b  = (const float*)p; break;
            case 32768: {
                int nxt = (i + 1 < n_in) ? in_sizes[i + 1] : -1;
                if (nxt == 128)      enc_W  = (const float*)p;
                else if (nxt == 256) conv_W = (const float*)p;
                else if (!enc_W)     enc_W  = (const float*)p;   // fallback: dict order
                else                 conv_W = (const float*)p;
                break;
            }
            default: break;
        }
    }
    float* out = (float*)d_out;

    float *deg, *dinv, *h, *tbuf, *agg;
    int* flag;
    cudaGetSymbolAddress((void**)&deg,  g_deg);
    cudaGetSymbolAddress((void**)&dinv, g_dinv);
    cudaGetSymbolAddress((void**)&h,    g_h);
    cudaGetSymbolAddress((void**)&tbuf, g_t);
    cudaGetSymbolAddress((void**)&agg,  g_agg);
    cudaGetSymbolAddress((void**)&flag, g_is32);

    const int T = 256;
    int nb_nodes = (N_NODES + T - 1) / T;
    int nb_edges = (N_EDGES + T - 1) / T;
    int nb_elems = (N_NODES * HIDDEN / 4 + T - 1) / T;
    int nb_scat  = (N_EDGES + 7) / 8;

    // edge dtype detection + normalization
    k_detect<<<1, 32>>>(ei, flag);
    k_deg_init<<<nb_nodes, T>>>(deg, N_NODES);
    k_deg_accum<<<nb_edges, T>>>(ei, deg, flag, N_EDGES);
    k_dinv<<<nb_nodes, T>>>(deg, dinv, N_NODES);

    // encoder: h = lrelu(x @ enc_W + enc_b)
    {
        dim3 grid(HIDDEN / 64, (N_NODES + 63) / 64);
        sgemm_kernel<<<grid, 256>>>(x, enc_W, enc_b, h, N_NODES, HIDDEN, IN_DIM, 1);
    }

    // 2 GCN conv layers
    for (int l = 0; l < 2; l++) {
        const float* W = conv_W + (size_t)l * HIDDEN * HIDDEN;
        const float* b = conv_b + (size_t)l * HIDDEN;
        dim3 grid(HIDDEN / 64, (N_NODES + 63) / 64);
        sgemm_kernel<<<grid, 256>>>(h, W, nullptr, tbuf, N_NODES, HIDDEN, HIDDEN, 0);
        k_selfinit<<<nb_elems, T>>>(tbuf, dinv, b, agg);
        k_scatter<<<nb_scat, T>>>(ei, dinv, tbuf, agg, flag, N_EDGES);
        k_lrelu<<<nb_elems, T>>>(agg, h);
    }

    // decoder: out = h @ dec_W + dec_b
    {
        dim3 grid(OUT_DIM / 64, (N_NODES + 63) / 64);
        sgemm_kernel<<<grid, 256>>>(h, dec_W, dec_b, out, N_NODES, OUT_DIM, HIDDEN, 0);
    }
}

// round 7
// speedup vs baseline: 1.8786x; 1.8786x over previous
#include <cuda_runtime.h>
#include <cstdint>

#define N_NODES 50000
#define N_EDGES 800000
#define IN_DIM  256
#define HIDDEN  128
#define OUT_DIM 64
#define NEG_SLOPE 0.1f

#define SCAN_B 256
#define NSCAN_BLOCKS ((N_NODES + SCAN_B - 1) / SCAN_B)   // 196

// ---------------- scratch (no allocations allowed) ----------------
__device__ __align__(16) float g_dinv[N_NODES];
__device__ __align__(16) float g_h   [N_NODES * HIDDEN];
__device__ __align__(16) float g_t   [N_NODES * HIDDEN];
__device__ int  g_cnt   [N_NODES];
__device__ int  g_cursor[N_NODES];
__device__ int  g_rowptr[N_NODES + 1];
__device__ int  g_bsum  [SCAN_B];
__device__ __align__(8) int2 g_edge [N_EDGES];   // {src, bitcast(dinv[src])}
__device__ int  g_is32;

// ---------------- edge index access (int32 or int64) ----------------
__device__ __forceinline__ int edge_at(const void* ei, int i, int is32, int half) {
    if (is32) return ((const int*)ei)[half * N_EDGES + i];
    return (int)((const long long*)ei)[half * N_EDGES + i];
}

__global__ void k_detect(const void* __restrict__ ei, int* __restrict__ flag) {
    if (threadIdx.x == 0 && blockIdx.x == 0) {
        const long long* p = (const long long*)ei;
        int is32 = 0;
        for (int i = 0; i < 64; i++) {
            long long v = p[i];
            if (v < 0 || v >= N_NODES) { is32 = 1; break; }
        }
        *flag = is32;
    }
}

// ---------------- CSR build ----------------
__global__ void k_hist_init(int* __restrict__ cnt, int* __restrict__ cur, int n) {
    int i = blockIdx.x * blockDim.x + threadIdx.x;
    if (i < n) { cnt[i] = 0; cur[i] = 0; }
}

__global__ void k_hist(const void* __restrict__ ei, int* __restrict__ cnt,
                       const int* __restrict__ flag, int e) {
    int i = blockIdx.x * blockDim.x + threadIdx.x;
    if (i >= e) return;
    int d = edge_at(ei, i, *flag, 1);
    if ((unsigned)d < N_NODES) atomicAdd(&cnt[d], 1);
}

__global__ void k_dinv(const int* __restrict__ cnt, float* __restrict__ dinv, int n) {
    int i = blockIdx.x * blockDim.x + threadIdx.x;
    if (i < n) dinv[i] = rsqrtf((float)(cnt[i] + 1));   // +1 self loop
}

// exclusive scan, 3 phases
__global__ void k_scan1(const int* __restrict__ cnt, int* __restrict__ rowptr,
                        int* __restrict__ bsum, int n) {
    __shared__ int s[SCAN_B];
    int i = blockIdx.x * SCAN_B + threadIdx.x;
    int v = (i < n) ? cnt[i] : 0;
    s[threadIdx.x] = v;
    __syncthreads();
    int acc = v;
#pragma unroll
    for (int off = 1; off < SCAN_B; off <<= 1) {
        int add = (threadIdx.x >= off) ? s[threadIdx.x - off] : 0;
        __syncthreads();
        acc += add;
        s[threadIdx.x] = acc;
        __syncthreads();
    }
    if (i < n) rowptr[i] = acc - v;              // local exclusive
    if (threadIdx.x == SCAN_B - 1) bsum[blockIdx.x] = acc;
}

__global__ void k_scan2(int* __restrict__ bsum, int nb) {
    __shared__ int s[SCAN_B];
    int v = (threadIdx.x < nb) ? bsum[threadIdx.x] : 0;
    s[threadIdx.x] = v;
    __syncthreads();
    int acc = v;
#pragma unroll
    for (int off = 1; off < SCAN_B; off <<= 1) {
        int add = (threadIdx.x >= off) ? s[threadIdx.x - off] : 0;
        __syncthreads();
        acc += add;
        s[threadIdx.x] = acc;
        __syncthreads();
    }
    if (threadIdx.x < nb) bsum[threadIdx.x] = acc - v;   // exclusive
}

__global__ void k_scan3(int* __restrict__ rowptr, const int* __restrict__ bsum, int n) {
    int i = blockIdx.x * SCAN_B + threadIdx.x;
    if (i < n) rowptr[i] += bsum[blockIdx.x];
    if (i == 0) rowptr[n] = N_EDGES;
}

__global__ void k_fill(const void* __restrict__ ei, const int* __restrict__ rowptr,
                       int* __restrict__ cur, const float* __restrict__ dinv,
                       int2* __restrict__ edge, const int* __restrict__ flag, int e) {
    int i = blockIdx.x * blockDim.x + threadIdx.x;
    if (i >= e) return;
    int is32 = *flag;
    int s = edge_at(ei, i, is32, 0);
    int d = edge_at(ei, i, is32, 1);
    if ((unsigned)s >= N_NODES || (unsigned)d >= N_NODES) return;
    int pos = rowptr[d] + atomicAdd(&cur[d], 1);
    edge[pos] = make_int2(s, __float_as_int(dinv[s]));
}

// ---------------- fused aggregation: one warp per dst node ----------------
// h[d] = lrelu( t[d]*dinv[d]^2 + bias + sum_e t[src_e]*dinv[src_e]*dinv[d] )
__global__ void __launch_bounds__(256) k_gather(
    const int* __restrict__ rowptr, const int2* __restrict__ edge,
    const float* __restrict__ dinv, const float* __restrict__ t,
    const float* __restrict__ bias, float* __restrict__ h, int n)
{
    int d = blockIdx.x * 8 + (threadIdx.x >> 5);
    if (d >= n) return;
    int lane = threadIdx.x & 31;
    float dd = dinv[d];

    float4 acc = ((const float4*)(t + (size_t)d * HIDDEN))[lane];
    float w0 = dd * dd;
    acc.x *= w0; acc.y *= w0; acc.z *= w0; acc.w *= w0;

    int j   = rowptr[d];
    int end = rowptr[d + 1];
    for (; j + 1 < end; j += 2) {
        int2 e0 = edge[j];
        int2 e1 = edge[j + 1];
        float wa = __int_as_float(e0.y) * dd;
        float wb = __int_as_float(e1.y) * dd;
        float4 v0 = ((const float4*)(t + (size_t)e0.x * HIDDEN))[lane];
        float4 v1 = ((const float4*)(t + (size_t)e1.x * HIDDEN))[lane];
        acc.x = fmaf(v0.x, wa, acc.x); acc.y = fmaf(v0.y, wa, acc.y);
        acc.z = fmaf(v0.z, wa, acc.z); acc.w = fmaf(v0.w, wa, acc.w);
        acc.x = fmaf(v1.x, wb, acc.x); acc.y = fmaf(v1.y, wb, acc.y);
        acc.z = fmaf(v1.z, wb, acc.z); acc.w = fmaf(v1.w, wb, acc.w);
    }
    if (j < end) {
        int2 e0 = edge[j];
        float wa = __int_as_float(e0.y) * dd;
        float4 v0 = ((const float4*)(t + (size_t)e0.x * HIDDEN))[lane];
        acc.x = fmaf(v0.x, wa, acc.x); acc.y = fmaf(v0.y, wa, acc.y);
        acc.z = fmaf(v0.z, wa, acc.z); acc.w = fmaf(v0.w, wa, acc.w);
    }

    float4 b = *(const float4*)(bias + lane * 4);
    acc.x += b.x; acc.y += b.y; acc.z += b.z; acc.w += b.w;
    acc.x = acc.x > 0.f ? acc.x : acc.x * NEG_SLOPE;
    acc.y = acc.y > 0.f ? acc.y : acc.y * NEG_SLOPE;
    acc.z = acc.z > 0.f ? acc.z : acc.z * NEG_SLOPE;
    acc.w = acc.w > 0.f ? acc.w : acc.w * NEG_SLOPE;
    ((float4*)(h + (size_t)d * HIDDEN))[lane] = acc;
}

// ---------------- SGEMM 128x128x16, 8x8/thread (N multiple of 128) ----------------
__global__ void __launch_bounds__(256) sgemm128(
    const float* __restrict__ A, const float* __restrict__ B,
    const float* __restrict__ bias, float* __restrict__ C,
    int M, int N, int K, int act)
{
    const int BM = 128, BN = 128, BK = 16;
    __shared__ float As[BK][BM];
    __shared__ float Bs[BK][BN];

    int t = threadIdx.x;
    int bm0 = blockIdx.y * BM;
    int bn0 = blockIdx.x * BN;

    int trow = t >> 4;     // 0..15 -> rows trow*8..+7
    int tcol = t & 15;     // 0..15 -> cols tcol*8..+7

    float acc[8][8];
#pragma unroll
    for (int i = 0; i < 8; i++)
#pragma unroll
        for (int j = 0; j < 8; j++) acc[i][j] = 0.f;

    for (int k0 = 0; k0 < K; k0 += BK) {
        // A tile: 128x16 = 512 float4, 2 per thread; store transposed
#pragma unroll
        for (int u = 0; u < 2; u++) {
            int idx = t + u * 256;
            int row = idx >> 2;            // 0..127
            int k4  = (idx & 3) * 4;       // 0,4,8,12
            int gr  = bm0 + row;
            float4 v = make_float4(0.f, 0.f, 0.f, 0.f);
            if (gr < M) v = *(const float4*)(A + (size_t)gr * K + k0 + k4);
            As[k4 + 0][row] = v.x;
            As[k4 + 1][row] = v.y;
            As[k4 + 2][row] = v.z;
            As[k4 + 3][row] = v.w;
        }
        // B tile: 16x128 = 512 float4, 2 per thread
#pragma unroll
        for (int u = 0; u < 2; u++) {
            int idx = t + u * 256;
            int br  = idx >> 5;            // 0..15
            int bc4 = (idx & 31) * 4;      // 0..124
            float4 v = *(const float4*)(B + (size_t)(k0 + br) * N + bn0 + bc4);
            *(float4*)&Bs[br][bc4] = v;
        }
        __syncthreads();

#pragma unroll
        for (int kk = 0; kk < BK; kk++) {
            float ar[8], br[8];
            *(float4*)&ar[0] = *(const float4*)&As[kk][trow * 8];
            *(float4*)&ar[4] = *(const float4*)&As[kk][trow * 8 + 4];
            *(float4*)&br[0] = *(const float4*)&Bs[kk][tcol * 8];
            *(float4*)&br[4] = *(const float4*)&Bs[kk][tcol * 8 + 4];
#pragma unroll
            for (int i = 0; i < 8; i++)
#pragma unroll
                for (int j = 0; j < 8; j++)
                    acc[i][j] = fmaf(ar[i], br[j], acc[i][j]);
        }
        __syncthreads();
    }

    float bv[8] = {0,0,0,0,0,0,0,0};
    if (bias) {
        *(float4*)&bv[0] = *(const float4*)(bias + bn0 + tcol * 8);
        *(float4*)&bv[4] = *(const float4*)(bias + bn0 + tcol * 8 + 4);
    }
#pragma unroll
    for (int i = 0; i < 8; i++) {
        int gr = bm0 + trow * 8 + i;
        if (gr >= M) continue;
        float o[8];
#pragma unroll
        for (int j = 0; j < 8; j++) {
            float v = acc[i][j] + bv[j];
            if (act) v = v > 0.f ? v : v * NEG_SLOPE;
            o[j] = v;
        }
        *(float4*)(C + (size_t)gr * N + bn0 + tcol * 8)     = *(float4*)&o[0];
        *(float4*)(C + (size_t)gr * N + bn0 + tcol * 8 + 4) = *(float4*)&o[4];
    }
}

// ---------------- SGEMM 64x64x16 (for dec, N=64) ----------------
__global__ void __launch_bounds__(256) sgemm64(
    const float* __restrict__ A, const float* __restrict__ B,
    const float* __restrict__ bias, float* __restrict__ C,
    int M, int N, int K, int act)
{
    const int BM = 64, BN = 64, BK = 16;
    __shared__ float As[BK][BM];
    __shared__ float Bs[BK][BN];

    int t = threadIdx.x;
    int bm0 = blockIdx.y * BM;
    int bn0 = blockIdx.x * BN;

    int a_row = t >> 2;
    int a_k4  = (t & 3) * 4;
    int b_row = t >> 4;
    int b_c4  = (t & 15) * 4;
    int trow = t >> 4;
    int tcol = t & 15;

    float acc[4][4];
#pragma unroll
    for (int i = 0; i < 4; i++)
#pragma unroll
        for (int j = 0; j < 4; j++) acc[i][j] = 0.f;

    for (int k0 = 0; k0 < K; k0 += BK) {
        {
            int gr = bm0 + a_row;
            float4 v = make_float4(0.f, 0.f, 0.f, 0.f);
            if (gr < M) v = *(const float4*)(A + (size_t)gr * K + k0 + a_k4);
            As[a_k4 + 0][a_row] = v.x;
            As[a_k4 + 1][a_row] = v.y;
            As[a_k4 + 2][a_row] = v.z;
            As[a_k4 + 3][a_row] = v.w;
        }
        {
            float4 v = *(const float4*)(B + (size_t)(k0 + b_row) * N + bn0 + b_c4);
            *(float4*)&Bs[b_row][b_c4] = v;
        }
        __syncthreads();

#pragma unroll
        for (int kk = 0; kk < BK; kk++) {
            float4 a = *(const float4*)&As[kk][trow * 4];
            float4 b = *(const float4*)&Bs[kk][tcol * 4];
            float ar[4] = {a.x, a.y, a.z, a.w};
            float br[4] = {b.x, b.y, b.z, b.w};
#pragma unroll
            for (int i = 0; i < 4; i++)
#pragma unroll
                for (int j = 0; j < 4; j++)
                    acc[i][j] = fmaf(ar[i], br[j], acc[i][j]);
        }
        __syncthreads();
    }

    float4 bv = make_float4(0.f, 0.f, 0.f, 0.f);
    if (bias) bv = *(const float4*)(bias + bn0 + tcol * 4);
#pragma unroll
    for (int i = 0; i < 4; i++) {
        int gr = bm0 + trow * 4 + i;
        if (gr >= M) continue;
        float4 o;
        o.x = acc[i][0] + bv.x;
        o.y = acc[i][1] + bv.y;
        o.z = acc[i][2] + bv.z;
        o.w = acc[i][3] + bv.w;
        if (act) {
            o.x = o.x > 0.f ? o.x : o.x * NEG_SLOPE;
            o.y = o.y > 0.f ? o.y : o.y * NEG_SLOPE;
            o.z = o.z > 0.f ? o.z : o.z * NEG_SLOPE;
            o.w = o.w > 0.f ? o.w : o.w * NEG_SLOPE;
        }
        *(float4*)(C + (size_t)gr * N + bn0 + tcol * 4) = o;
    }
}

// ---------------- launch ----------------
extern "C" void kernel_launch(void* const* d_in, const int* in_sizes, int n_in,
                              void* d_out, int out_size)
{
    const float *x = 0, *enc_W = 0, *enc_b = 0, *conv_W = 0, *conv_b = 0, *dec_W = 0, *dec_b = 0;
    const void  *ei = 0;
    for (int i = 0; i < n_in; i++) {
        int sz = in_sizes[i];
        const void* p = d_in[i];
        switch (sz) {
            case 12800000: x      = (const float*)p; break;
            case 1600000:  ei     = p;               break;
            case 128:      enc_b  = (const float*)p; break;
            case 256:      conv_b = (const float*)p; break;
            case 8192:     dec_W  = (const float*)p; break;
            case 64:       dec_b  = (const float*)p; break;
            case 32768: {
                int nxt = (i + 1 < n_in) ? in_sizes[i + 1] : -1;
                if (nxt == 128)      enc_W  = (const float*)p;
                else if (nxt == 256) conv_W = (const float*)p;
                else if (!enc_W)     enc_W  = (const float*)p;
                else                 conv_W = (const float*)p;
                break;
            }
            default: break;
        }
    }
    float* out = (float*)d_out;

    float *dinv, *h, *tbuf;
    int *cnt, *cur, *rowptr, *bsum, *flag;
    int2 *edge;
    cudaGetSymbolAddress((void**)&dinv,   g_dinv);
    cudaGetSymbolAddress((void**)&h,      g_h);
    cudaGetSymbolAddress((void**)&tbuf,   g_t);
    cudaGetSymbolAddress((void**)&cnt,    g_cnt);
    cudaGetSymbolAddress((void**)&cur,    g_cursor);
    cudaGetSymbolAddress((void**)&rowptr, g_rowptr);
    cudaGetSymbolAddress((void**)&bsum,   g_bsum);
    cudaGetSymbolAddress((void**)&edge,   g_edge);
    cudaGetSymbolAddress((void**)&flag,   g_is32);

    const int T = 256;
    int nb_nodes = (N_NODES + T - 1) / T;
    int nb_edges = (N_EDGES + T - 1) / T;

    // CSR build + normalization
    k_detect<<<1, 32>>>(ei, flag);
    k_hist_init<<<nb_nodes, T>>>(cnt, cur, N_NODES);
    k_hist<<<nb_edges, T>>>(ei, cnt, flag, N_EDGES);
    k_dinv<<<nb_nodes, T>>>(cnt, dinv, N_NODES);
    k_scan1<<<NSCAN_BLOCKS, SCAN_B>>>(cnt, rowptr, bsum, N_NODES);
    k_scan2<<<1, SCAN_B>>>(bsum, NSCAN_BLOCKS);
    k_scan3<<<NSCAN_BLOCKS, SCAN_B>>>(rowptr, bsum, N_NODES);
    k_fill<<<nb_edges, T>>>(ei, rowptr, cur, dinv, edge, flag, N_EDGES);

    // encoder: h = lrelu(x @ enc_W + enc_b)
    {
        dim3 grid(HIDDEN / 128, (N_NODES + 127) / 128);
        sgemm128<<<grid, 256>>>(x, enc_W, enc_b, h, N_NODES, HIDDEN, IN_DIM, 1);
    }

    // 2 GCN conv layers: t = h @ W, then fused gather(+bias+lrelu) -> h
    for (int l = 0; l < 2; l++) {
        const float* W = conv_W + (size_t)l * HIDDEN * HIDDEN;
        const float* b = conv_b + (size_t)l * HIDDEN;
        dim3 grid(HIDDEN / 128, (N_NODES + 127) / 128);
        sgemm128<<<grid, 256>>>(h, W, nullptr, tbuf, N_NODES, HIDDEN, HIDDEN, 0);
        k_gather<<<(N_NODES + 7) / 8, 256>>>(rowptr, edge, dinv, tbuf, b, h, N_NODES);
    }

    // decoder: out = h @ dec_W + dec_b
    {
        dim3 grid(OUT_DIM / 64, (N_NODES + 63) / 64);
        sgemm64<<<grid, 256>>>(h, dec_W, dec_b, out, N_NODES, OUT_DIM, HIDDEN, 0);
    }
}

// round 11
// speedup vs baseline: 2.2446x; 1.1948x over previous
#include <cuda_runtime.h>
#include <cstdint>

#define N_NODES 50000
#define N_EDGES 800000
#define IN_DIM  256
#define HIDDEN  128
#define OUT_DIM 64
#define NEG_SLOPE 0.1f

#define SCAN_B 256
#define NSCAN_BLOCKS ((N_NODES + SCAN_B - 1) / SCAN_B)   // 196

// ---------------- scratch (no allocations allowed) ----------------
__device__ __align__(16) float g_dinv[N_NODES];
__device__ __align__(16) float g_h   [N_NODES * HIDDEN];
__device__ __align__(16) float g_t   [N_NODES * HIDDEN];
__device__ int  g_cnt   [N_NODES];
__device__ int  g_cursor[N_NODES];
__device__ int  g_rowptr[N_NODES + 1];
__device__ int  g_bsum  [SCAN_B];
__device__ __align__(8) int2 g_edge [N_EDGES];   // {src, bitcast(dinv[src])}
__device__ int  g_is32;

// ---------------- packed f32x2 helpers ----------------
__device__ __forceinline__ unsigned long long pack_dup(float a) {
    unsigned long long r;
    asm("mov.b64 %0, {%1, %1};" : "=l"(r) : "r"(__float_as_int(a)));
    return r;
}
__device__ __forceinline__ void fma_f32x2(unsigned long long& acc,
                                          unsigned long long a, unsigned long long b) {
    asm("fma.rn.f32x2 %0, %1, %2, %0;" : "+l"(acc) : "l"(a), "l"(b));
}
__device__ __forceinline__ void unpack_f32x2(unsigned long long v, float& lo, float& hi) {
    int a, b;
    asm("mov.b64 {%0, %1}, %2;" : "=r"(a), "=r"(b) : "l"(v));
    lo = __int_as_float(a); hi = __int_as_float(b);
}

// ---------------- edge index access (int32 or int64) ----------------
__device__ __forceinline__ int edge_at(const void* ei, int i, int is32, int half) {
    if (is32) return ((const int*)ei)[half * N_EDGES + i];
    return (int)((const long long*)ei)[half * N_EDGES + i];
}

__global__ void k_detect(const void* __restrict__ ei, int* __restrict__ flag) {
    if (threadIdx.x == 0 && blockIdx.x == 0) {
        const long long* p = (const long long*)ei;
        int is32 = 0;
        for (int i = 0; i < 64; i++) {
            long long v = p[i];
            if (v < 0 || v >= N_NODES) { is32 = 1; break; }
        }
        *flag = is32;
    }
}

// ---------------- CSR build ----------------
__global__ void k_hist_init(int* __restrict__ cnt, int* __restrict__ cur, int n) {
    int i = blockIdx.x * blockDim.x + threadIdx.x;
    if (i < n) { cnt[i] = 0; cur[i] = 0; }
}

__global__ void k_hist(const void* __restrict__ ei, int* __restrict__ cnt,
                       const int* __restrict__ flag, int e) {
    int i = blockIdx.x * blockDim.x + threadIdx.x;
    if (i >= e) return;
    int d = edge_at(ei, i, *flag, 1);
    if ((unsigned)d < N_NODES) atomicAdd(&cnt[d], 1);
}

__global__ void k_dinv(const int* __restrict__ cnt, float* __restrict__ dinv, int n) {
    int i = blockIdx.x * blockDim.x + threadIdx.x;
    if (i < n) dinv[i] = rsqrtf((float)(cnt[i] + 1));   // +1 self loop
}

// exclusive scan, 3 phases
__global__ void k_scan1(const int* __restrict__ cnt, int* __restrict__ rowptr,
                        int* __restrict__ bsum, int n) {
    __shared__ int s[SCAN_B];
    int i = blockIdx.x * SCAN_B + threadIdx.x;
    int v = (i < n) ? cnt[i] : 0;
    s[threadIdx.x] = v;
    __syncthreads();
    int acc = v;
#pragma unroll
    for (int off = 1; off < SCAN_B; off <<= 1) {
        int add = (threadIdx.x >= off) ? s[threadIdx.x - off] : 0;
        __syncthreads();
        acc += add;
        s[threadIdx.x] = acc;
        __syncthreads();
    }
    if (i < n) rowptr[i] = acc - v;              // local exclusive
    if (threadIdx.x == SCAN_B - 1) bsum[blockIdx.x] = acc;
}

__global__ void k_scan2(int* __restrict__ bsum, int nb) {
    __shared__ int s[SCAN_B];
    int v = (threadIdx.x < nb) ? bsum[threadIdx.x] : 0;
    s[threadIdx.x] = v;
    __syncthreads();
    int acc = v;
#pragma unroll
    for (int off = 1; off < SCAN_B; off <<= 1) {
        int add = (threadIdx.x >= off) ? s[threadIdx.x - off] : 0;
        __syncthreads();
        acc += add;
        s[threadIdx.x] = acc;
        __syncthreads();
    }
    if (threadIdx.x < nb) bsum[threadIdx.x] = acc - v;   // exclusive
}

__global__ void k_scan3(int* __restrict__ rowptr, const int* __restrict__ bsum, int n) {
    int i = blockIdx.x * SCAN_B + threadIdx.x;
    if (i < n) rowptr[i] += bsum[blockIdx.x];
    if (i == 0) rowptr[n] = N_EDGES;
}

__global__ void k_fill(const void* __restrict__ ei, const int* __restrict__ rowptr,
                       int* __restrict__ cur, const float* __restrict__ dinv,
                       int2* __restrict__ edge, const int* __restrict__ flag, int e) {
    int i = blockIdx.x * blockDim.x + threadIdx.x;
    if (i >= e) return;
    int is32 = *flag;
    int s = edge_at(ei, i, is32, 0);
    int d = edge_at(ei, i, is32, 1);
    if ((unsigned)s >= N_NODES || (unsigned)d >= N_NODES) return;
    int pos = rowptr[d] + atomicAdd(&cur[d], 1);
    edge[pos] = make_int2(s, __float_as_int(dinv[s]));
}

// ---------------- fused aggregation: one warp per dst node ----------------
// h[d] = lrelu( t[d]*dinv[d]^2 + bias + sum_e t[src_e]*dinv[src_e]*dinv[d] )
__global__ void __launch_bounds__(256) k_gather(
    const int* __restrict__ rowptr, const int2* __restrict__ edge,
    const float* __restrict__ dinv, const float* __restrict__ t,
    const float* __restrict__ bias, float* __restrict__ h, int n)
{
    int d = blockIdx.x * 8 + (threadIdx.x >> 5);
    if (d >= n) return;
    int lane = threadIdx.x & 31;
    float dd = dinv[d];

    float4 acc = ((const float4*)(t + (size_t)d * HIDDEN))[lane];
    float w0 = dd * dd;
    acc.x *= w0; acc.y *= w0; acc.z *= w0; acc.w *= w0;

    int j   = rowptr[d];
    int end = rowptr[d + 1];
    // 4-way unrolled: 4 independent gathers in flight
    for (; j + 3 < end; j += 4) {
        int2 e0 = edge[j];
        int2 e1 = edge[j + 1];
        int2 e2 = edge[j + 2];
        int2 e3 = edge[j + 3];
        float4 v0 = ((const float4*)(t + (size_t)e0.x * HIDDEN))[lane];
        float4 v1 = ((const float4*)(t + (size_t)e1.x * HIDDEN))[lane];
        float4 v2 = ((const float4*)(t + (size_t)e2.x * HIDDEN))[lane];
        float4 v3 = ((const float4*)(t + (size_t)e3.x * HIDDEN))[lane];
        float wa = __int_as_float(e0.y) * dd;
        float wb = __int_as_float(e1.y) * dd;
        float wc = __int_as_float(e2.y) * dd;
        float wd = __int_as_float(e3.y) * dd;
        acc.x = fmaf(v0.x, wa, acc.x); acc.y = fmaf(v0.y, wa, acc.y);
        acc.z = fmaf(v0.z, wa, acc.z); acc.w = fmaf(v0.w, wa, acc.w);
        acc.x = fmaf(v1.x, wb, acc.x); acc.y = fmaf(v1.y, wb, acc.y);
        acc.z = fmaf(v1.z, wb, acc.z); acc.w = fmaf(v1.w, wb, acc.w);
        acc.x = fmaf(v2.x, wc, acc.x); acc.y = fmaf(v2.y, wc, acc.y);
        acc.z = fmaf(v2.z, wc, acc.z); acc.w = fmaf(v2.w, wc, acc.w);
        acc.x = fmaf(v3.x, wd, acc.x); acc.y = fmaf(v3.y, wd, acc.y);
        acc.z = fmaf(v3.z, wd, acc.z); acc.w = fmaf(v3.w, wd, acc.w);
    }
    for (; j < end; j++) {
        int2 e0 = edge[j];
        float wa = __int_as_float(e0.y) * dd;
        float4 v0 = ((const float4*)(t + (size_t)e0.x * HIDDEN))[lane];
        acc.x = fmaf(v0.x, wa, acc.x); acc.y = fmaf(v0.y, wa, acc.y);
        acc.z = fmaf(v0.z, wa, acc.z); acc.w = fmaf(v0.w, wa, acc.w);
    }

    float4 b = *(const float4*)(bias + lane * 4);
    acc.x += b.x; acc.y += b.y; acc.z += b.z; acc.w += b.w;
    acc.x = acc.x > 0.f ? acc.x : acc.x * NEG_SLOPE;
    acc.y = acc.y > 0.f ? acc.y : acc.y * NEG_SLOPE;
    acc.z = acc.z > 0.f ? acc.z : acc.z * NEG_SLOPE;
    acc.w = acc.w > 0.f ? acc.w : acc.w * NEG_SLOPE;
    ((float4*)(h + (size_t)d * HIDDEN))[lane] = acc;
}

// ---------------- SGEMM 128x128x16, 8x8/thread, packed f32x2 FMA ----------------
__global__ void __launch_bounds__(256) sgemm128(
    const float* __restrict__ A, const float* __restrict__ B,
    const float* __restrict__ bias, float* __restrict__ C,
    int M, int N, int K, int act)
{
    const int BM = 128, BN = 128, BK = 16;
    __shared__ float As[BK][BM];
    __shared__ float Bs[BK][BN];

    int t = threadIdx.x;
    int bm0 = blockIdx.y * BM;
    int bn0 = blockIdx.x * BN;

    int trow = t >> 4;     // 0..15 -> rows trow*8..+7
    int tcol = t & 15;     // 0..15 -> cols tcol*8..+7

    // accp[i][j] = packed pair (col 2j, col 2j+1) of logical acc row i
    unsigned long long accp[8][4];
#pragma unroll
    for (int i = 0; i < 8; i++)
#pragma unroll
        for (int j = 0; j < 4; j++) accp[i][j] = 0ULL;

    for (int k0 = 0; k0 < K; k0 += BK) {
#pragma unroll
        for (int u = 0; u < 2; u++) {
            int idx = t + u * 256;
            int row = idx >> 2;            // 0..127
            int k4  = (idx & 3) * 4;       // 0,4,8,12
            int gr  = bm0 + row;
            float4 v = make_float4(0.f, 0.f, 0.f, 0.f);
            if (gr < M) v = *(const float4*)(A + (size_t)gr * K + k0 + k4);
            As[k4 + 0][row] = v.x;
            As[k4 + 1][row] = v.y;
            As[k4 + 2][row] = v.z;
            As[k4 + 3][row] = v.w;
        }
#pragma unroll
        for (int u = 0; u < 2; u++) {
            int idx = t + u * 256;
            int br  = idx >> 5;            // 0..15
            int bc4 = (idx & 31) * 4;      // 0..124
            float4 v = *(const float4*)(B + (size_t)(k0 + br) * N + bn0 + bc4);
            *(float4*)&Bs[br][bc4] = v;
        }
        __syncthreads();

#pragma unroll
        for (int kk = 0; kk < BK; kk++) {
            float ar[8];
            *(float4*)&ar[0] = *(const float4*)&As[kk][trow * 8];
            *(float4*)&ar[4] = *(const float4*)&As[kk][trow * 8 + 4];
            ulonglong2 q0 = *(const ulonglong2*)&Bs[kk][tcol * 8];
            ulonglong2 q1 = *(const ulonglong2*)&Bs[kk][tcol * 8 + 4];
            unsigned long long bb[4] = {q0.x, q0.y, q1.x, q1.y};
#pragma unroll
            for (int i = 0; i < 8; i++) {
                unsigned long long aa = pack_dup(ar[i]);
#pragma unroll
                for (int j = 0; j < 4; j++)
                    fma_f32x2(accp[i][j], aa, bb[j]);
            }
        }
        __syncthreads();
    }

    float bv[8] = {0,0,0,0,0,0,0,0};
    if (bias) {
        *(float4*)&bv[0] = *(const float4*)(bias + bn0 + tcol * 8);
        *(float4*)&bv[4] = *(const float4*)(bias + bn0 + tcol * 8 + 4);
    }
#pragma unroll
    for (int i = 0; i < 8; i++) {
        int gr = bm0 + trow * 8 + i;
        if (gr >= M) continue;
        float o[8];
#pragma unroll
        for (int j = 0; j < 4; j++)
            unpack_f32x2(accp[i][j], o[2 * j], o[2 * j + 1]);
#pragma unroll
        for (int j = 0; j < 8; j++) {
            float v = o[j] + bv[j];
            if (act) v = v > 0.f ? v : v * NEG_SLOPE;
            o[j] = v;
        }
        *(float4*)(C + (size_t)gr * N + bn0 + tcol * 8)     = *(float4*)&o[0];
        *(float4*)(C + (size_t)gr * N + bn0 + tcol * 8 + 4) = *(float4*)&o[4];
    }
}

// ---------------- SGEMM 64x64x16 (dec, N=64), packed f32x2 FMA ----------------
__global__ void __launch_bounds__(256) sgemm64(
    const float* __restrict__ A, const float* __restrict__ B,
    const float* __restrict__ bias, float* __restrict__ C,
    int M, int N, int K, int act)
{
    const int BM = 64, BN = 64, BK = 16;
    __shared__ float As[BK][BM];
    __shared__ float Bs[BK][BN];

    int t = threadIdx.x;
    int bm0 = blockIdx.y * BM;
    int bn0 = blockIdx.x * BN;

    int a_row = t >> 2;
    int a_k4  = (t & 3) * 4;
    int b_row = t >> 4;
    int b_c4  = (t & 15) * 4;
    int trow = t >> 4;
    int tcol = t & 15;

    unsigned long long accp[4][2];
#pragma unroll
    for (int i = 0; i < 4; i++) { accp[i][0] = 0ULL; accp[i][1] = 0ULL; }

    for (int k0 = 0; k0 < K; k0 += BK) {
        {
            int gr = bm0 + a_row;
            float4 v = make_float4(0.f, 0.f, 0.f, 0.f);
            if (gr < M) v = *(const float4*)(A + (size_t)gr * K + k0 + a_k4);
            As[a_k4 + 0][a_row] = v.x;
            As[a_k4 + 1][a_row] = v.y;
            As[a_k4 + 2][a_row] = v.z;
            As[a_k4 + 3][a_row] = v.w;
        }
        {
            float4 v = *(const float4*)(B + (size_t)(k0 + b_row) * N + bn0 + b_c4);
            *(float4*)&Bs[b_row][b_c4] = v;
        }
        __syncthreads();

#pragma unroll
        for (int kk = 0; kk < BK; kk++) {
            float4 a = *(const float4*)&As[kk][trow * 4];
            ulonglong2 q = *(const ulonglong2*)&Bs[kk][tcol * 4];
            unsigned long long bb[2] = {q.x, q.y};
            float ar[4] = {a.x, a.y, a.z, a.w};
#pragma unroll
            for (int i = 0; i < 4; i++) {
                unsigned long long aa = pack_dup(ar[i]);
                fma_f32x2(accp[i][0], aa, bb[0]);
                fma_f32x2(accp[i][1], aa, bb[1]);
            }
        }
        __syncthreads();
    }

    float4 bv = make_float4(0.f, 0.f, 0.f, 0.f);
    if (bias) bv = *(const float4*)(bias + bn0 + tcol * 4);
#pragma unroll
    for (int i = 0; i < 4; i++) {
        int gr = bm0 + trow * 4 + i;
        if (gr >= M) continue;
        float4 o;
        unpack_f32x2(accp[i][0], o.x, o.y);
        unpack_f32x2(accp[i][1], o.z, o.w);
        o.x += bv.x; o.y += bv.y; o.z += bv.z; o.w += bv.w;
        if (act) {
            o.x = o.x > 0.f ? o.x : o.x * NEG_SLOPE;
            o.y = o.y > 0.f ? o.y : o.y * NEG_SLOPE;
            o.z = o.z > 0.f ? o.z : o.z * NEG_SLOPE;
            o.w = o.w > 0.f ? o.w : o.w * NEG_SLOPE;
        }
        *(float4*)(C + (size_t)gr * N + bn0 + tcol * 4) = o;
    }
}

// ---------------- launch ----------------
extern "C" void kernel_launch(void* const* d_in, const int* in_sizes, int n_in,
                              void* d_out, int out_size)
{
    const float *x = 0, *enc_W = 0, *enc_b = 0, *conv_W = 0, *conv_b = 0, *dec_W = 0, *dec_b = 0;
    const void  *ei = 0;
    for (int i = 0; i < n_in; i++) {
        int sz = in_sizes[i];
        const void* p = d_in[i];
        switch (sz) {
            case 12800000: x      = (const float*)p; break;
            case 1600000:  ei     = p;               break;
            case 128:      enc_b  = (const float*)p; break;
            case 256:      conv_b = (const float*)p; break;
            case 8192:     dec_W  = (const float*)p; break;
            case 64:       dec_b  = (const float*)p; break;
            case 32768: {
                int nxt = (i + 1 < n_in) ? in_sizes[i + 1] : -1;
                if (nxt == 128)      enc_W  = (const float*)p;
                else if (nxt == 256) conv_W = (const float*)p;
                else if (!enc_W)     enc_W  = (const float*)p;
                else                 conv_W = (const float*)p;
                break;
            }
            default: break;
        }
    }
    float* out = (float*)d_out;

    float *dinv, *h, *tbuf;
    int *cnt, *cur, *rowptr, *bsum, *flag;
    int2 *edge;
    cudaGetSymbolAddress((void**)&dinv,   g_dinv);
    cudaGetSymbolAddress((void**)&h,      g_h);
    cudaGetSymbolAddress((void**)&tbuf,   g_t);
    cudaGetSymbolAddress((void**)&cnt,    g_cnt);
    cudaGetSymbolAddress((void**)&cur,    g_cursor);
    cudaGetSymbolAddress((void**)&rowptr, g_rowptr);
    cudaGetSymbolAddress((void**)&bsum,   g_bsum);
    cudaGetSymbolAddress((void**)&edge,   g_edge);
    cudaGetSymbolAddress((void**)&flag,   g_is32);

    const int T = 256;
    int nb_nodes = (N_NODES + T - 1) / T;
    int nb_edges = (N_EDGES + T - 1) / T;

    // CSR build + normalization
    k_detect<<<1, 32>>>(ei, flag);
    k_hist_init<<<nb_nodes, T>>>(cnt, cur, N_NODES);
    k_hist<<<nb_edges, T>>>(ei, cnt, flag, N_EDGES);
    k_dinv<<<nb_nodes, T>>>(cnt, dinv, N_NODES);
    k_scan1<<<NSCAN_BLOCKS, SCAN_B>>>(cnt, rowptr, bsum, N_NODES);
    k_scan2<<<1, SCAN_B>>>(bsum, NSCAN_BLOCKS);
    k_scan3<<<NSCAN_BLOCKS, SCAN_B>>>(rowptr, bsum, N_NODES);
    k_fill<<<nb_edges, T>>>(ei, rowptr, cur, dinv, edge, flag, N_EDGES);

    // encoder: h = lrelu(x @ enc_W + enc_b)
    {
        dim3 grid(HIDDEN / 128, (N_NODES + 127) / 128);
        sgemm128<<<grid, 256>>>(x, enc_W, enc_b, h, N_NODES, HIDDEN, IN_DIM, 1);
    }

    // 2 GCN conv layers: t = h @ W, then fused gather(+bias+lrelu) -> h
    for (int l = 0; l < 2; l++) {
        const float* W = conv_W + (size_t)l * HIDDEN * HIDDEN;
        const float* b = conv_b + (size_t)l * HIDDEN;
        dim3 grid(HIDDEN / 128, (N_NODES + 127) / 128);
        sgemm128<<<grid, 256>>>(h, W, nullptr, tbuf, N_NODES, HIDDEN, HIDDEN, 0);
        k_gather<<<(N_NODES + 7) / 8, 256>>>(rowptr, edge, dinv, tbuf, b, h, N_NODES);
    }

    // decoder: out = h @ dec_W + dec_b
    {
        dim3 grid(OUT_DIM / 64, (N_NODES + 63) / 64);
        sgemm64<<<grid, 256>>>(h, dec_W, dec_b, out, N_NODES, OUT_DIM, HIDDEN, 0);
    }
}